// round 12
// baseline (speedup 1.0000x reference)
#include <cuda_runtime.h>
#include <stdint.h>

// Problem constants (fixed by the reference setup)
#define Bn 16
#define Pn 784
#define Dn 10000
#define Ln 1000
#define Cn 10

#define WSTRIDE 320    // padded words per row (320*32 = 10240 >= 10000)
#define NSLAB   10     // 10 slabs of 32 words
#define NCH     7      // 7 pixel chunks of 112 (8 warps x 14)
#define NBP     8      // 8 batch pairs
#define NGROUP  (NBP * NSLAB)         // 80 (bp, slab) groups
#define NCTA_A  (NGROUP * NCH)        // 560 phase-A CTAs

// Scratch (allocation-free: device globals)
__device__ uint32_t g_vbits[Ln * WSTRIDE];     // sign bits of value_weight
__device__ uint32_t g_pbits[Pn * WSTRIDE];     // sign bits of position_weight
__device__ uint32_t g_idx2[NBP * Pn];          // packed level idx pair (lo|hi<<16)
__device__ uint32_t g_chunk[NCTA_A * 2 * 7 * 32]; // 7-plane chunk partials
__device__ float    g_partial[NSLAB * Bn * Cn];
__device__ int      g_gctr[NGROUP];            // per-group arrival counters
__device__ int      g_ctr2;                    // group completion counter

// ---------------------------------------------------------------------------
// Kernel 1: compute packed idx pairs, pack sign bits of both bipolar tables.
// Permuted bit layout: word w, bit l  <->  dim d = (w>>2)*128 + l*4 + (w&3).
// Warp-task = 512 dims: 4 lane-contiguous float4 loads (fully coalesced),
// sign extraction via FSETP feeding VOTE directly, 16 ballots -> 16 words.
// ---------------------------------------------------------------------------
__global__ void __launch_bounds__(256) pack_kernel(const float* __restrict__ x,
                                                   const float* __restrict__ posw,
                                                   const float* __restrict__ valw)
{
    const int tid     = blockIdx.x * blockDim.x + threadIdx.x;
    const int nthread = gridDim.x * blockDim.x;

    // packed level indices: idx = clamp(rint(x*999), 0, 999)  (half-to-even)
    for (int i = tid; i < NBP * Pn; i += nthread) {
        int bp = i / Pn, p = i - bp * Pn;
        int qa = (int)rintf(x[(2 * bp)     * Pn + p] * 999.0f);
        int qb = (int)rintf(x[(2 * bp + 1) * Pn + p] * 999.0f);
        qa = min(max(qa, 0), Ln - 1);
        qb = min(max(qb, 0), Ln - 1);
        g_idx2[i] = (uint32_t)qa | ((uint32_t)qb << 16);
    }

    const int lane   = threadIdx.x & 31;
    const int warpId = tid >> 5;
    const int nWarps = nthread >> 5;
    const int totalTasks = (Ln + Pn) * 20;   // 20 x 512-dim tasks per row

    for (int task = warpId; task < totalTasks; task += nWarps) {
        int row = task / 20;
        int s   = task - row * 20;
        const float* src;
        uint32_t* dst;
        if (row < Ln) {
            src = valw + (size_t)row * Dn;
            dst = g_vbits + row * WSTRIDE;
        } else {
            src = posw + (size_t)(row - Ln) * Dn;
            dst = g_pbits + (row - Ln) * WSTRIDE;
        }

        uint32_t myword = 0;
        if (s < 19) {
            float4 v0 = *reinterpret_cast<const float4*>(src + s * 512 +   0 + lane * 4);
            float4 v1 = *reinterpret_cast<const float4*>(src + s * 512 + 128 + lane * 4);
            float4 v2 = *reinterpret_cast<const float4*>(src + s * 512 + 256 + lane * 4);
            float4 v3 = *reinterpret_cast<const float4*>(src + s * 512 + 384 + lane * 4);
#define PK(sub, vv)                                                          \
            {                                                                \
                uint32_t b0 = __ballot_sync(0xffffffffu, (vv).x < 0.0f);     \
                uint32_t b1 = __ballot_sync(0xffffffffu, (vv).y < 0.0f);     \
                uint32_t b2 = __ballot_sync(0xffffffffu, (vv).z < 0.0f);     \
                uint32_t b3 = __ballot_sync(0xffffffffu, (vv).w < 0.0f);     \
                if (lane == (sub)*4 + 0) myword = b0;                        \
                if (lane == (sub)*4 + 1) myword = b1;                        \
                if (lane == (sub)*4 + 2) myword = b2;                        \
                if (lane == (sub)*4 + 3) myword = b3;                        \
            }
            PK(0, v0) PK(1, v1) PK(2, v2) PK(3, v3)
#undef PK
        } else {
            // tail task (dims 9728..10239): per-lane validity
#pragma unroll
            for (int sub = 0; sub < 4; sub++) {
                int d0 = s * 512 + sub * 128 + lane * 4;
                bool valid = d0 < Dn;            // Dn % 4 == 0
                float4 v = make_float4(0.f, 0.f, 0.f, 0.f);
                if (valid) v = *reinterpret_cast<const float4*>(src + d0);
                uint32_t b0 = __ballot_sync(0xffffffffu, valid && v.x < 0.0f);
                uint32_t b1 = __ballot_sync(0xffffffffu, valid && v.y < 0.0f);
                uint32_t b2 = __ballot_sync(0xffffffffu, valid && v.z < 0.0f);
                uint32_t b3 = __ballot_sync(0xffffffffu, valid && v.w < 0.0f);
                if (lane == sub * 4 + 0) myword = b0;
                if (lane == sub * 4 + 1) myword = b1;
                if (lane == sub * 4 + 2) myword = b2;
                if (lane == sub * 4 + 3) myword = b3;
            }
        }
        if (lane < 16) dst[s * 16 + lane] = myword;      // coalesced 64B
    }
}

// ---------------------------------------------------------------------------
__device__ __forceinline__ void fadd(uint32_t a, uint32_t b, uint32_t cin,
                                     uint32_t& s, uint32_t& cout)
{
    uint32_t t = a ^ b;
    s    = t ^ cin;
    cout = (a & b) | (cin & t);
}

// 7:3 compress t[0..6] and merge into 4-plane counter cp[0..3] (max 14)
__device__ __forceinline__ void csa7_merge4(const uint32_t* t, uint32_t* cp)
{
    uint32_t s1, c1, s2, c2, s3, c3, s4, c4;
    fadd(t[0], t[1], t[2], s1, c1);
    fadd(t[3], t[4], t[5], s2, c2);
    fadd(s1,  s2,  t[6],  s3, c3);
    fadd(c1,  c2,  c3,    s4, c4);
    uint32_t carry = cp[0] & s3; cp[0] ^= s3;
    uint32_t s, co;
    fadd(cp[1], s4, carry, s, co); cp[1] = s; carry = co;
    fadd(cp[2], c4, carry, s, co); cp[2] = s; carry = co;
    cp[3] ^= carry;
}

// enc bit = 1 iff count < 392 (392 = 0b0110001000), 10 bit-planes
__device__ __forceinline__ uint32_t thr392(const uint32_t* c)
{
    uint32_t eq = ~0u, lt = 0u;
    eq &= ~c[9];
    lt |= eq & ~c[8]; eq &= c[8];
    lt |= eq & ~c[7]; eq &= c[7];
    eq &= ~c[6]; eq &= ~c[5]; eq &= ~c[4];
    lt |= eq & ~c[3];
    return lt;
}

// ---------------------------------------------------------------------------
// Kernel 2: CTA = (batch-pair, slab of 32 words, chunk of 112 pixels),
// 256 threads = 8 warps x 14 pixels, 560 CTAs (~4/SM resident).
// Lane holds ONE word (LDG.32, ~46 regs, no spills); the pbits stream is
// loaded once per pixel and shared by both batches; packed idx pairs give
// both levels in one smem read. 4-plane CSA -> 3-round tree (7 planes) ->
// chunk partial. 7th CTA of each (bp,slab) group sums chunks -> threshold
// -> enc -> coalesced classify. 80th group completion writes out.
// Deterministic; int atomics only.
// ---------------------------------------------------------------------------
__global__ void __launch_bounds__(256) hdc_main_kernel(const float* __restrict__ cw,
                                                       float* __restrict__ out)
{
    const int bp   = blockIdx.x / (NSLAB * NCH);
    const int r0   = blockIdx.x - bp * (NSLAB * NCH);
    const int slab = r0 / NCH;
    const int ch   = r0 - slab * NCH;
    const int grp  = bp * NSLAB + slab;
    const int tid  = threadIdx.x;
    const int lane = tid & 31;
    const int wsub = tid >> 5;                   // 0..7

    __shared__ uint32_t sIdx2[112];
    __shared__ uint32_t sBuf[4][2][7][32];       // [src][b][plane][lane]
    __shared__ uint32_t sEnc[2][32];
    __shared__ int      sDoB, sLast;

    if (tid < 112) sIdx2[tid] = g_idx2[bp * Pn + ch * 112 + tid];
    __syncthreads();

    const int w  = slab * 32 + lane;             // this lane's word
    const int p0 = ch * 112 + wsub * 14;         // global first pixel of warp

    // counters: [batch][plane], counts <= 14
    uint32_t cnt[2][4];
#pragma unroll
    for (int b = 0; b < 2; b++)
#pragma unroll
        for (int j = 0; j < 4; j++) cnt[b][j] = 0u;

#pragma unroll
    for (int g = 0; g < 2; g++) {                // 2 groups of 7 pixels
        const int pg = p0 + g * 7;
        const int lg = wsub * 14 + g * 7;        // local pixel in chunk
        uint32_t pr[7], q[7], va[7], vb[7];
#pragma unroll
        for (int k = 0; k < 7; k++) pr[k] = sIdx2[lg + k];
#pragma unroll
        for (int k = 0; k < 7; k++)
            q[k] = __ldg(g_pbits + (pg + k) * WSTRIDE + w);
#pragma unroll
        for (int k = 0; k < 7; k++)
            va[k] = __ldg(g_vbits + (pr[k] & 0xffffu) * WSTRIDE + w);
#pragma unroll
        for (int k = 0; k < 7; k++)
            vb[k] = __ldg(g_vbits + (pr[k] >> 16) * WSTRIDE + w);

        uint32_t t[7];
#pragma unroll
        for (int k = 0; k < 7; k++) t[k] = va[k] ^ q[k];
        csa7_merge4(t, cnt[0]);
#pragma unroll
        for (int k = 0; k < 7; k++) t[k] = vb[k] ^ q[k];
        csa7_merge4(t, cnt[1]);
    }

    // ---- 3-round tree reduction across 8 warps: 4 -> 7 planes ----
    uint32_t a[2][7];
#pragma unroll
    for (int b = 0; b < 2; b++) {
#pragma unroll
        for (int j = 0; j < 4; j++) a[b][j] = cnt[b][j];
        a[b][4] = a[b][5] = a[b][6] = 0u;
    }

#pragma unroll
    for (int r = 0; r < 3; r++) {
        const int half = 4 >> r;                 // 4,2,1 readers
        const int np   = 4 + r;                  // planes valid in sources
        if (wsub >= half && wsub < 2 * half) {
#pragma unroll
            for (int b = 0; b < 2; b++)
#pragma unroll
                for (int j = 0; j < 7; j++)
                    if (j < np) sBuf[wsub - half][b][j][lane] = a[b][j];
        }
        __syncthreads();
        if (wsub < half) {
#pragma unroll
            for (int b = 0; b < 2; b++) {
                uint32_t cx = 0u;
#pragma unroll
                for (int j = 0; j < 7; j++) {
                    if (j < np) {
                        uint32_t s, co;
                        fadd(a[b][j], sBuf[wsub][b][j][lane], cx, s, co);
                        a[b][j] = s; cx = co;
                    } else if (j == np) {
                        a[b][j] = cx;
                    }
                }
            }
        }
        __syncthreads();
    }

    if (wsub == 0) {                             // write 7-plane chunk partial
#pragma unroll
        for (int b = 0; b < 2; b++)
#pragma unroll
            for (int j = 0; j < 7; j++)
                g_chunk[((blockIdx.x * 2 + b) * 7 + j) * 32 + lane] = a[b][j];
    }
    __syncthreads();

    // ---- group arrival: 7th CTA of this (bp,slab) runs phase B ----
    if (tid == 0) {
        __threadfence();
        int prev = atomicAdd(&g_gctr[grp], 1);
        sDoB = (prev == NCH - 1);
        if (sDoB) g_gctr[grp] = 0;               // reset for next replay
    }
    __syncthreads();
    if (!sDoB) return;

    __threadfence();                             // acquire peer chunk partials

    // ---- phase B: warps 0,1 (one per batch) sum 7 chunks -> enc ----
    if (wsub < 2) {
        uint32_t s[10];
#pragma unroll
        for (int j = 0; j < 10; j++) s[j] = 0u;
#pragma unroll
        for (int c2 = 0; c2 < NCH; c2++) {
            const int cta = grp * NCH + c2;
            uint32_t cx = 0u;
#pragma unroll
            for (int j = 0; j < 7; j++) {
                uint32_t v = __ldg(g_chunk + ((cta * 2 + wsub) * 7 + j) * 32 + lane);
                uint32_t ss, co;
                fadd(s[j], v, cx, ss, co);
                s[j] = ss; cx = co;
            }
#pragma unroll
            for (int j = 7; j < 10; j++) {
                uint32_t nc = s[j] ^ cx; cx &= s[j]; s[j] = nc;
            }
        }
        sEnc[wsub][lane] = thr392(s);
    }
    __syncthreads();

    // ---- coalesced classify: unit u = b*10+c over dims [slab*1024, +1024).
    // float4 at d0 = slab*1024 + i*128 + lane*4 maps to bit lane of local
    // words i*4+{0..3}; enc words broadcast from smem.
    for (int u = wsub; u < 2 * Cn; u += 8) {
        const int b = u / Cn, c = u - (u / Cn) * Cn;
        const float* __restrict__ wrow = cw + c * Dn + slab * 1024;
        float acc = 0.0f;
#pragma unroll
        for (int i = 0; i < 8; i++) {
            int d0 = slab * 1024 + i * 128 + lane * 4;
            if (d0 < Dn) {                       // Dn%4==0 -> whole float4 valid
                uint32_t w0 = sEnc[b][i * 4 + 0];
                uint32_t w1 = sEnc[b][i * 4 + 1];
                uint32_t w2 = sEnc[b][i * 4 + 2];
                uint32_t w3 = sEnc[b][i * 4 + 3];
                float4 v = *reinterpret_cast<const float4*>(wrow + i * 128 + lane * 4);
                acc += ((w0 >> lane) & 1u) ? v.x : -v.x;
                acc += ((w1 >> lane) & 1u) ? v.y : -v.y;
                acc += ((w2 >> lane) & 1u) ? v.z : -v.z;
                acc += ((w3 >> lane) & 1u) ? v.w : -v.w;
            }
        }
        // deterministic fixed-order warp reduction
#pragma unroll
        for (int off = 16; off >= 1; off >>= 1)
            acc += __shfl_xor_sync(0xffffffffu, acc, off);
        if (lane == 0) g_partial[(slab * Bn + (bp * 2 + b)) * Cn + c] = acc;
    }

    // ---- 80th group completion writes the final output ----
    __syncthreads();
    if (tid == 0) {
        __threadfence();
        int prev = atomicAdd(&g_ctr2, 1);
        sLast = (prev == NGROUP - 1);
    }
    __syncthreads();
    if (sLast) {
        __threadfence();
        if (tid < Bn * Cn) {
            float s = 0.0f;
#pragma unroll
            for (int sl = 0; sl < NSLAB; sl++) s += g_partial[sl * Bn * Cn + tid];
            out[tid] = s;
        }
        if (tid == 0) g_ctr2 = 0;                // reset for next replay
    }
}

// ---------------------------------------------------------------------------
extern "C" void kernel_launch(void* const* d_in, const int* in_sizes, int n_in,
                              void* d_out, int out_size)
{
    const float* x    = (const float*)d_in[0];   // [16,28,28]
    const float* posw = (const float*)d_in[1];   // [784,10000]
    const float* valw = (const float*)d_in[2];   // [1000,10000]
    const float* cw   = (const float*)d_in[3];   // [10,10000]
    float* out = (float*)d_out;                  // [16,10]

    pack_kernel<<<1184, 256>>>(x, posw, valw);
    hdc_main_kernel<<<NCTA_A, 256>>>(cw, out);
}